// round 16
// baseline (speedup 1.0000x reference)
#include <cuda_runtime.h>
#include <cstdint>

// ---------------------------------------------------------------------------
// CML2DWithStats, round 16: r15 base (cluster-4, DS = beta*drive smem tile,
// split cluster barrier) with the DSMEM halo converted from PULL to PUSH.
//
//   g_{t+1} = clamp( conv3x3( m_t, K' ) + BETA*drive ),  m = g*(1-g)
//   K' = R*(1-BETA)*(EPS*K + (1-EPS)*delta_center)
//
// Cluster (4,1,1) per plane; rank = 64-row strip. Per-CTA smem:
//   MB0/MB1: two 66-row mapped buffers (rows 0..63 own, 64 = top halo slot,
//            65 = bottom halo slot), DS: 64-row beta*drive tile.
// Halo transport: after computing boundary pair B, warp ty0 PUSHES its row-0
// mapped values into the up-neighbor's slot 65 of the SAME buffer (Mout) via
// mapa + st.shared::cluster (issue-only, no latency stall); ty15 pushes row
// 63 into the down-neighbor's slot 64. Push precedes cluster.arrive
// (release); the consumer reads its LOCAL slot next step after cluster.wait
// (acquire) with a plain 29-cycle LDS. This removes the ~215-cycle DSMEM
// pull stall that sat on the barrier-critical warps every step.
// Step: pair B -> pushes -> arrive -> pair A -> __syncthreads -> wait.
// Init seeds MB0 slots from gmem drive (rows rbase-1 / rbase+64) and zeroes
// MB1 slots; edge-strip slots stay zero forever (zero padding).
// ---------------------------------------------------------------------------

#define R_PARAM  3.9f
#define EPS_P    0.3f
#define BETA_P   0.15f
#define NSTEPS   15
#define CLAMP_LO 1e-4f
#define CLAMP_HI (1.0f - 1e-4f)

constexpr int W      = 256;
constexpr int RCTA   = 64;
constexpr int NSTRIP = 4;
constexpr int BROWS  = 66;                 // 64 own + 2 halo slots
constexpr int TXN    = 32;
constexpr int TYN    = 16;
constexpr int NTHR   = TXN * TYN;          // 512
constexpr int NPLANE = W * 256;
constexpr long long NTOT = 16LL * 8 * NPLANE;
constexpr int BUF        = BROWS * W;                  // 16896 floats
constexpr int DS_OFF     = 2 * BUF;                    // DS tile offset (floats)
constexpr int SMEM_BYTES = (2 * BUF + RCTA * W) * 4;   // 200704 B

__device__ __forceinline__ float clampg(float v) {
    return fminf(fmaxf(v, CLAMP_LO), CLAMP_HI);
}

__device__ __forceinline__ uint32_t smem_u32(const void* p) {
    uint32_t a;
    asm("{ .reg .u64 t; cvta.to.shared.u64 t, %1; cvt.u32.u64 %0, t; }"
        : "=r"(a) : "l"(p));
    return a;
}

// remote (cluster) shared store of one float4
__device__ __forceinline__ void dsmem_st4(uint32_t my_addr, uint32_t rank, float4 v) {
    uint32_t ra;
    asm volatile("mapa.shared::cluster.u32 %0, %1, %2;"
                 : "=r"(ra) : "r"(my_addr), "r"(rank));
    asm volatile("st.shared::cluster.v4.f32 [%0], {%1, %2, %3, %4};"
                 :: "r"(ra), "f"(v.x), "f"(v.y), "f"(v.z), "f"(v.w) : "memory");
}

#define CLUSTER_ARRIVE() \
    asm volatile("barrier.cluster.arrive.aligned;" ::: "memory")
#define CLUSTER_WAIT() \
    asm volatile("barrier.cluster.wait.aligned;"   ::: "memory")
#define CLUSTER_BAR()  do { CLUSTER_ARRIVE(); CLUSTER_WAIT(); } while (0)

__global__ void __launch_bounds__(NTHR, 1) __cluster_dims__(NSTRIP, 1, 1)
cml_push_kernel(const float* __restrict__ drive,
                const float* __restrict__ Klocal,
                float* __restrict__ out)
{
    extern __shared__ float sm[];
    float* MB0 = sm;
    float* MB1 = sm + BUF;
    float* DS  = sm + DS_OFF;              // 64 rows of beta*drive

    const int tx = threadIdx.x;
    const int ty = threadIdx.y;
    const int strip = blockIdx.x;          // cluster rank 0..3
    const int c     = blockIdx.y;
    const int b     = blockIdx.z;
    const int x4    = tx * 4;
    const int x0    = tx * 8;
    const int rbase = strip * RCTA;

    // Folded kernel K' = R*(1-BETA)*(EPS*K + (1-EPS)*delta)
    float kk[3][3];
    {
        const float* kc = Klocal + c * 9;
        #pragma unroll
        for (int j = 0; j < 3; ++j)
            #pragma unroll
            for (int i = 0; i < 3; ++i) {
                float v = EPS_P * kc[j * 3 + i];
                if (j == 1 && i == 1) v += (1.0f - EPS_P);
                kk[j][i] = R_PARAM * (1.0f - BETA_P) * v;
            }
    }

    const long long plane = (long long)(b * 8 + c) * NPLANE;
    const float* dpl = drive + plane;

    // Pair assignment: pair B holds the cross-CTA boundary rows
    //   ty==0  -> pB = 0  (rows 0,1; B0 = halo slot 64)
    //   ty==15 -> pB = 31 (rows 62,63; B3 = halo slot 65)
    const int pA = (ty == 0) ? 16 : ty;          // 1..16
    const int pB = (ty == 0) ? 0  : ty + 16;     // 0, 17..31
    const int A0 = 2 * pA - 1, A1 = 2 * pA, A2 = 2 * pA + 1, A3 = 2 * pA + 2;
    const int B0 = (pB == 0)  ? 64 : 2 * pB - 1;
    const int B1 = 2 * pB,     B2 = 2 * pB + 1;
    const int B3 = (pB == 31) ? 65 : 2 * pB + 2;
    const int irA = rbase + 2 * pA;
    const int irB = rbase + 2 * pB;

    // ---- init: MB0 rows 0..63 <- mapped(drive); DS <- beta*drive;
    //      MB0 halo slots <- mapped(drive halo rows) or 0; MB1 slots <- 0 ----
    #pragma unroll
    for (int k = 0; k < 4; ++k) {
        int r = ty + TYN * k;                   // 0..63
        const float* dr = dpl + (long long)(rbase + r) * W + x0;
        float4 dA = *reinterpret_cast<const float4*>(dr);
        float4 dB = *reinterpret_cast<const float4*>(dr + 4);

        float4 mA, mB;
        mA.x = fmaf(-dA.x, dA.x, dA.x);  mA.y = fmaf(-dA.y, dA.y, dA.y);
        mA.z = fmaf(-dA.z, dA.z, dA.z);  mA.w = fmaf(-dA.w, dA.w, dA.w);
        mB.x = fmaf(-dB.x, dB.x, dB.x);  mB.y = fmaf(-dB.y, dB.y, dB.y);
        mB.z = fmaf(-dB.z, dB.z, dB.z);  mB.w = fmaf(-dB.w, dB.w, dB.w);
        float* p0 = MB0 + r * W;
        *reinterpret_cast<float4*>(p0 + x4)       = mA;
        *reinterpret_cast<float4*>(p0 + 128 + x4) = mB;

        float4 bA = make_float4(BETA_P * dA.x, BETA_P * dA.y,
                                BETA_P * dA.z, BETA_P * dA.w);
        float4 bB = make_float4(BETA_P * dB.x, BETA_P * dB.y,
                                BETA_P * dB.z, BETA_P * dB.w);
        float* pd = DS + r * W;
        *reinterpret_cast<float4*>(pd + x4)       = bA;
        *reinterpret_cast<float4*>(pd + 128 + x4) = bB;
    }
    {
        float4 z = make_float4(0.f, 0.f, 0.f, 0.f);
        if (ty == 0) {
            // MB1 top slot always zeroed (interior: overwritten by push
            // before first read; edge strip: must stay zero)
            *reinterpret_cast<float4*>(MB1 + 64 * W + x4)       = z;
            *reinterpret_cast<float4*>(MB1 + 64 * W + 128 + x4) = z;
            float4 hA = z, hB = z;
            if (strip > 0) {
                const float* dr = dpl + (long long)(rbase - 1) * W + x0;
                float4 dA = *reinterpret_cast<const float4*>(dr);
                float4 dB = *reinterpret_cast<const float4*>(dr + 4);
                hA.x = fmaf(-dA.x, dA.x, dA.x);  hA.y = fmaf(-dA.y, dA.y, dA.y);
                hA.z = fmaf(-dA.z, dA.z, dA.z);  hA.w = fmaf(-dA.w, dA.w, dA.w);
                hB.x = fmaf(-dB.x, dB.x, dB.x);  hB.y = fmaf(-dB.y, dB.y, dB.y);
                hB.z = fmaf(-dB.z, dB.z, dB.z);  hB.w = fmaf(-dB.w, dB.w, dB.w);
            }
            *reinterpret_cast<float4*>(MB0 + 64 * W + x4)       = hA;
            *reinterpret_cast<float4*>(MB0 + 64 * W + 128 + x4) = hB;
        } else if (ty == TYN - 1) {
            *reinterpret_cast<float4*>(MB1 + 65 * W + x4)       = z;
            *reinterpret_cast<float4*>(MB1 + 65 * W + 128 + x4) = z;
            float4 hA = z, hB = z;
            if (strip < NSTRIP - 1) {
                const float* dr = dpl + (long long)(rbase + 64) * W + x0;
                float4 dA = *reinterpret_cast<const float4*>(dr);
                float4 dB = *reinterpret_cast<const float4*>(dr + 4);
                hA.x = fmaf(-dA.x, dA.x, dA.x);  hA.y = fmaf(-dA.y, dA.y, dA.y);
                hA.z = fmaf(-dA.z, dA.z, dA.z);  hA.w = fmaf(-dA.w, dA.w, dA.w);
                hB.x = fmaf(-dB.x, dB.x, dB.x);  hB.y = fmaf(-dB.y, dB.y, dB.y);
                hB.z = fmaf(-dB.z, dB.z, dB.z);  hB.w = fmaf(-dB.w, dB.w, dB.w);
            }
            *reinterpret_cast<float4*>(MB0 + 65 * W + x4)       = hA;
            *reinterpret_cast<float4*>(MB0 + 65 * W + 128 + x4) = hB;
        }
    }
    // orders init (incl. MB1 slot zeroing) before any step-0 pushes
    CLUSTER_BAR();

    // stats: pair slots A and B. [rowInPair*8 + i]
    float sumA[16], ssqA[16], sumB[16], ssqB[16];
    #pragma unroll
    for (int i = 0; i < 16; ++i) {
        sumA[i] = 0.f; ssqA[i] = 0.f; sumB[i] = 0.f; ssqB[i] = 0.f;
    }

    #define ACCROW(acc, cc)                                                    \
        {                                                                      \
            float c0 = (cc)[0], c1 = (cc)[1], c2 = (cc)[2];                    \
            acc[0] = fmaf(c0, lm, fmaf(c1, m0, fmaf(c2, m1, acc[0])));         \
            acc[1] = fmaf(c0, m0, fmaf(c1, m1, fmaf(c2, m2, acc[1])));         \
            acc[2] = fmaf(c0, m1, fmaf(c1, m2, fmaf(c2, m3, acc[2])));         \
            acc[3] = fmaf(c0, m2, fmaf(c1, m3, fmaf(c2, m4, acc[3])));         \
            acc[4] = fmaf(c0, m3, fmaf(c1, m4, fmaf(c2, m5, acc[4])));         \
            acc[5] = fmaf(c0, m4, fmaf(c1, m5, fmaf(c2, m6, acc[5])));         \
            acc[6] = fmaf(c0, m5, fmaf(c1, m6, fmaf(c2, m7, acc[6])));         \
            acc[7] = fmaf(c0, m6, fmaf(c1, m7, fmaf(c2, rm, acc[7])));         \
        }

    #define LOAD_MROW(Min, slot)                                               \
        const float* rp = (Min) + (slot) * W;                                  \
        float4 qa = *reinterpret_cast<const float4*>(rp + x4);                 \
        float4 qb = *reinterpret_cast<const float4*>(rp + 128 + x4);           \
        float m0 = qa.x, m1 = qa.y, m2 = qa.z, m3 = qa.w;                      \
        float m4 = qb.x, m5 = qb.y, m6 = qb.z, m7 = qb.w;                      \
        float lm = __shfl_up_sync(0xffffffffu, m7, 1);                         \
        float rm = __shfl_down_sync(0xffffffffu, m0, 1);                       \
        if (tx == 0)  lm = 0.f;                                                \
        if (tx == 31) rm = 0.f;

    #define PAIR_CONV(Min, R0, R1, R2, R3, acc0, acc1)                         \
        {                                                                      \
            { LOAD_MROW(Min, R0)  ACCROW(acc0, kk[0]) }                        \
            { LOAD_MROW(Min, R1)  ACCROW(acc0, kk[1]) ACCROW(acc1, kk[0]) }    \
            { LOAD_MROW(Min, R2)  ACCROW(acc0, kk[2]) ACCROW(acc1, kk[1]) }    \
            { LOAD_MROW(Min, R3)  ACCROW(acc1, kk[2]) }                        \
        }

    // acc <- DS row (beta*drive) via LDS
    #define LOAD_DS_ACC(rr, acc)                                               \
        {                                                                      \
            const float* pd = DS + (rr) * W;                                   \
            float4 aA = *reinterpret_cast<const float4*>(pd + x4);             \
            float4 aB = *reinterpret_cast<const float4*>(pd + 128 + x4);       \
            acc[0] = aA.x;  acc[1] = aA.y;  acc[2] = aA.z;  acc[3] = aA.w;     \
            acc[4] = aB.x;  acc[5] = aB.y;  acc[6] = aB.z;  acc[7] = aB.w;     \
        }

    // epilogue: clamp, stats, map (acc becomes mm), store
    #define PAIR_EPILOG(Mout, orow, acc0, acc1, sumP, ssqP)                    \
        {                                                                      \
            _Pragma("unroll")                                                  \
            for (int i = 0; i < 8; ++i) {                                      \
                float g = clampg(acc0[i]);                                     \
                sumP[i] += g;  ssqP[i] = fmaf(g, g, ssqP[i]);                  \
                acc0[i] = fmaf(-g, g, g);                                      \
            }                                                                  \
            _Pragma("unroll")                                                  \
            for (int i = 0; i < 8; ++i) {                                      \
                float g = clampg(acc1[i]);                                     \
                sumP[i + 8] += g;  ssqP[i + 8] = fmaf(g, g, ssqP[i + 8]);      \
                acc1[i] = fmaf(-g, g, g);                                      \
            }                                                                  \
            float* op0 = (Mout) + (orow) * W;                                  \
            float* op1 = (Mout) + ((orow) + 1) * W;                            \
            *reinterpret_cast<float4*>(op0 + x4)       = make_float4(acc0[0], acc0[1], acc0[2], acc0[3]); \
            *reinterpret_cast<float4*>(op0 + 128 + x4) = make_float4(acc0[4], acc0[5], acc0[6], acc0[7]); \
            *reinterpret_cast<float4*>(op1 + x4)       = make_float4(acc1[0], acc1[1], acc1[2], acc1[3]); \
            *reinterpret_cast<float4*>(op1 + 128 + x4) = make_float4(acc1[4], acc1[5], acc1[6], acc1[7]); \
        }

    // ---- steps 0..13: pair B -> pushes -> arrive -> pair A -> sync -> wait ----
    #pragma unroll 1
    for (int t = 0; t < NSTEPS - 1; ++t) {
        float* Min  = (t & 1) ? MB1 : MB0;
        float* Mout = (t & 1) ? MB0 : MB1;

        {   // pair B (boundary rows). Halo slot reads are plain local LDS.
            float acc0[8], acc1[8];
            LOAD_DS_ACC(2 * pB, acc0)
            LOAD_DS_ACC(2 * pB + 1, acc1)
            PAIR_CONV(Min, B0, B1, B2, B3, acc0, acc1)
            PAIR_EPILOG(Mout, 2 * pB, acc0, acc1, sumB, ssqB)

            // PUSH boundary mapped rows into the neighbor's halo slot of the
            // SAME buffer (Mout): visible to them after the barrier.
            if (ty == 0) {
                if (strip > 0) {
                    uint32_t a = smem_u32(Mout + 65 * W + x4);
                    dsmem_st4(a, (uint32_t)(strip - 1),
                              make_float4(acc0[0], acc0[1], acc0[2], acc0[3]));
                    dsmem_st4(a + 512, (uint32_t)(strip - 1),
                              make_float4(acc0[4], acc0[5], acc0[6], acc0[7]));
                }
            } else if (ty == TYN - 1) {
                if (strip < NSTRIP - 1) {
                    uint32_t a = smem_u32(Mout + 64 * W + x4);
                    dsmem_st4(a, (uint32_t)(strip + 1),
                              make_float4(acc1[0], acc1[1], acc1[2], acc1[3]));
                    dsmem_st4(a + 512, (uint32_t)(strip + 1),
                              make_float4(acc1[4], acc1[5], acc1[6], acc1[7]));
                }
            }
        }
        CLUSTER_ARRIVE();                  // releases boundary rows + pushes

        {   // pair A (interior) hides the barrier propagation
            float acc0[8], acc1[8];
            LOAD_DS_ACC(2 * pA, acc0)
            LOAD_DS_ACC(2 * pA + 1, acc1)
            PAIR_CONV(Min, A0, A1, A2, A3, acc0, acc1)
            PAIR_EPILOG(Mout, 2 * pA, acc0, acc1, sumA, ssqA)
        }
        __syncthreads();                   // intra-CTA ordering of Mout
        CLUSTER_WAIT();                    // ~free by now
    }

    // ---- final step t=14 (reads MB0; slots pushed during step 13) ----
    {
        float* Min = MB0;
        const float inv = 1.0f / (float)NSTEPS;

        #pragma unroll
        for (int pp = 0; pp < 2; ++pp) {
            const int irr  = pp ? irB : irA;
            float* sumP = pp ? sumB : sumA;
            float* ssqP = pp ? ssqB : ssqA;

            float acc0[8] = {0.f,0.f,0.f,0.f,0.f,0.f,0.f,0.f};
            float acc1[8] = {0.f,0.f,0.f,0.f,0.f,0.f,0.f,0.f};
            if (pp == 0) { PAIR_CONV(Min, A0, A1, A2, A3, acc0, acc1) }
            else         { PAIR_CONV(Min, B0, B1, B2, B3, acc0, acc1) }

            #pragma unroll
            for (int half = 0; half < 2; ++half) {
                float* acc = half ? acc1 : acc0;
                const int off = half * 8;
                const int ir  = irr + half;
                long long idx = plane + (long long)ir * W + x0;

                // raw drive from global (needed exactly for delta)
                const float* dr = dpl + (long long)ir * W + x0;
                float4 dA = *reinterpret_cast<const float4*>(dr);
                float4 dB = *reinterpret_cast<const float4*>(dr + 4);
                float dv[8] = { dA.x, dA.y, dA.z, dA.w, dB.x, dB.y, dB.z, dB.w };

                float g[8], mean[8], var[8], del[8];
                #pragma unroll
                for (int i = 0; i < 8; ++i) {
                    g[i] = clampg(fmaf(BETA_P, dv[i], acc[i]));
                    float s  = sumP[off + i] + g[i];
                    float sq = fmaf(g[i], g[i], ssqP[off + i]);
                    mean[i] = s * inv;
                    var[i]  = fmaf(-mean[i], mean[i], sq * inv);
                    del[i]  = g[i] - dv[i];
                }
                *reinterpret_cast<float4*>(out + idx)                = make_float4(g[0], g[1], g[2], g[3]);
                *reinterpret_cast<float4*>(out + idx + 4)            = make_float4(g[4], g[5], g[6], g[7]);
                *reinterpret_cast<float4*>(out + NTOT + idx)         = make_float4(mean[0], mean[1], mean[2], mean[3]);
                *reinterpret_cast<float4*>(out + NTOT + idx + 4)     = make_float4(mean[4], mean[5], mean[6], mean[7]);
                *reinterpret_cast<float4*>(out + 2 * NTOT + idx)     = make_float4(var[0], var[1], var[2], var[3]);
                *reinterpret_cast<float4*>(out + 2 * NTOT + idx + 4) = make_float4(var[4], var[5], var[6], var[7]);
                *reinterpret_cast<float4*>(out + 3 * NTOT + idx)     = make_float4(del[0], del[1], del[2], del[3]);
                *reinterpret_cast<float4*>(out + 3 * NTOT + idx + 4) = make_float4(del[4], del[5], del[6], del[7]);
                *reinterpret_cast<float4*>(out + 4 * NTOT + idx)     = make_float4(del[0], del[1], del[2], del[3]);
                *reinterpret_cast<float4*>(out + 4 * NTOT + idx + 4) = make_float4(del[4], del[5], del[6], del[7]);
            }
        }
    }
    // no trailing cluster barrier needed: there are no cross-CTA READS, and
    // all cross-CTA pushes completed before the step-13 barrier.
}

extern "C" void kernel_launch(void* const* d_in, const int* in_sizes, int n_in,
                              void* d_out, int out_size)
{
    const float* drive  = (const float*)d_in[0];   // [16,8,256,256] f32
    const float* Klocal = (const float*)d_in[1];   // [8,1,3,3] f32
    float* out = (float*)d_out;                    // 5 x [16,8,256,256] f32

    cudaFuncSetAttribute(cml_push_kernel,
                         cudaFuncAttributeMaxDynamicSharedMemorySize, SMEM_BYTES);

    dim3 grid(NSTRIP, 8, 16);          // 4 strips (1 cluster/plane) x 8 ch x 16 b
    dim3 block(TXN, TYN);              // 512 threads
    cml_push_kernel<<<grid, block, SMEM_BYTES>>>(drive, Klocal, out);
}